// round 1
// baseline (speedup 1.0000x reference)
#include <cuda_runtime.h>
#include <math.h>

#define BB 16
#define MM 32
#define HH 256
#define WW 256
#define NN 65536      // HH*WW
#define CC 27
#define T1 256        // threads for hist kernel
#define STRIDE 29     // padded hist stride (odd -> lane base is a bank permutation)

// ---- scratch (device globals; no allocation allowed) ----
__device__ __align__(16) unsigned char g_sem8[BB * NN];  // packed semantic classes
__device__ float g_hist[BB * MM * CC];                   // written by unique blocks, no atomics
__device__ float g_inter[BB];
__device__ float g_union[BB];
__device__ float g_dbc;

// ---------------------------------------------------------------------------
// Kernel 0: pack sem int32 -> uint8 (1 MiB, stays L2-resident for 32x reuse),
// and zero the small accumulators.
// ---------------------------------------------------------------------------
__global__ __launch_bounds__(256) void pack_kernel(const int* __restrict__ sem) {
    int i = blockIdx.x * 256 + threadIdx.x;            // over NN*BB/4 uchar4
    int4 v = ((const int4*)sem)[i];
    uchar4 o;
    o.x = (unsigned char)v.x; o.y = (unsigned char)v.y;
    o.z = (unsigned char)v.z; o.w = (unsigned char)v.w;
    ((uchar4*)g_sem8)[i] = o;
    if (blockIdx.x == 0) {
        int t = threadIdx.x;
        if (t < BB) { g_inter[t] = 0.f; g_union[t] = 0.f; }
        if (t == 0) g_dbc = 0.f;
    }
}

// ---------------------------------------------------------------------------
// Kernel 1: per-(b,m) masked histogram via per-thread-private smem histograms.
// grid = 512 blocks (one per (b,m)), 256 threads.
// Each thread owns a 29-float padded slot: bank = (29*lane + c) mod 32.
// ---------------------------------------------------------------------------
__global__ __launch_bounds__(T1) void hist_kernel(const float* __restrict__ masks) {
    __shared__ float s_hist[T1 * STRIDE];     // 256*29*4 = 29,696 B
    __shared__ float s_red[T1 / 32][CC];

    const int block = blockIdx.x;             // block = b*32 + m
    const int b     = block >> 5;
    const int tid   = threadIdx.x;
    const int lane  = tid & 31;
    const int wid   = tid >> 5;

    float* my = s_hist + tid * STRIDE;
#pragma unroll
    for (int c = 0; c < CC; c++) my[c] = 0.f;

    const float4* mp = (const float4*)masks + (size_t)block * (NN / 4);
    const uchar4* sp = (const uchar4*)(g_sem8 + (size_t)b * NN);

#pragma unroll 4
    for (int j = 0; j < NN / 4 / T1; j++) {   // 64 iterations, 4 elems each
        int i = tid + j * T1;
        float4 v = mp[i];
        uchar4 cl = sp[i];
        my[cl.x] += v.x;
        my[cl.y] += v.y;
        my[cl.z] += v.z;
        my[cl.w] += v.w;
    }
    __syncwarp();

    // warp reduce: lane l (<27) sums class l across the warp's 32 private copies
    if (lane < CC) {
        const float* wb = s_hist + wid * 32 * STRIDE;
        float s = 0.f;
#pragma unroll
        for (int k = 0; k < 32; k++) s += wb[k * STRIDE + lane];
        s_red[wid][lane] = s;
    }
    __syncthreads();

    if (tid < CC) {
        float t = 0.f;
#pragma unroll
        for (int w = 0; w < T1 / 32; w++) t += s_red[w][tid];
        g_hist[block * CC + tid] = t;         // unique writer per block: plain store
    }
}

// ---------------------------------------------------------------------------
// Kernel 2: boundary + depth-boundary-coherence losses (elementwise + reduce).
// grid = B*H blocks (one image row each), 256 threads (one per column).
// ---------------------------------------------------------------------------
__global__ __launch_bounds__(256) void pixel_kernel(const float* __restrict__ masks,
                                                    const float* __restrict__ depth) {
    const int b = blockIdx.x >> 8;
    const int y = blockIdx.x & 255;
    const int x = threadIdx.x;
    const int n = (y << 8) | x;
    const size_t idx = ((size_t)b << 16) + (size_t)n;

    const unsigned char* sb = g_sem8 + ((size_t)b << 16);
    int s  = sb[n];
    int sl = x ? sb[n - 1]  : s;
    int su = y ? sb[n - WW] : s;
    float semb = (s != sl || s != su) ? 1.f : 0.f;

    const float* m0 = masks + ((size_t)b * MM) * NN;   // m = 0 plane
    float mm = m0[n];
    float ml = x ? m0[n - 1]  : mm;
    float mu = y ? m0[n - WW] : mm;
    float instb = (fabsf(mm - ml) > 0.3f || fabsf(mm - mu) > 0.3f) ? 1.f : 0.f;

    float inter = semb * instb;
    float uni   = fmaxf(semb, instb);

    float d  = depth[idx];
    float dl = x ? depth[idx - 1]  : d;
    float du = y ? depth[idx - WW] : d;
    float gx = d - dl, gy = d - du;
    float ss = gx * gx + gy * gy;
    float db = sqrtf(fmaxf(ss, 1e-24f));
    float dbc = fminf(db, 2.f);
    float contrib = (1.f + 3.f * dbc) * (1.f - semb) * dbc;

    // block reduction
#pragma unroll
    for (int o = 16; o > 0; o >>= 1) {
        inter   += __shfl_down_sync(0xffffffffu, inter,   o);
        uni     += __shfl_down_sync(0xffffffffu, uni,     o);
        contrib += __shfl_down_sync(0xffffffffu, contrib, o);
    }
    __shared__ float r0[8], r1[8], r2[8];
    int lane = threadIdx.x & 31, wid = threadIdx.x >> 5;
    if (lane == 0) { r0[wid] = inter; r1[wid] = uni; r2[wid] = contrib; }
    __syncthreads();
    if (threadIdx.x == 0) {
        float a = 0.f, u = 0.f, c2 = 0.f;
#pragma unroll
        for (int w = 0; w < 8; w++) { a += r0[w]; u += r1[w]; c2 += r2[w]; }
        atomicAdd(&g_inter[b], a);
        atomicAdd(&g_union[b], u);
        atomicAdd(&g_dbc, c2);
    }
}

// ---------------------------------------------------------------------------
// Kernel 3: finalize — entropies, means, the 4 output scalars.
// 1 block, 512 threads (one per (b,m)).
// ---------------------------------------------------------------------------
__global__ __launch_bounds__(512) void finalize_kernel(float* __restrict__ out) {
    const int tid = threadIdx.x;     // (b,m) pair index, 0..511
    float h[CC];
    float msum = 1e-6f;
#pragma unroll
    for (int c = 0; c < CC; c++) { h[c] = g_hist[tid * CC + c]; msum += h[c]; }
    float inv = 1.f / msum;
    float ent = 0.f;
#pragma unroll
    for (int c = 0; c < CC; c++) {
        float p = h[c] * inv;
        p = fminf(fmaxf(p, 1e-7f), 1.f);
        if (p > 1e-6f) ent -= p * logf(p + 1e-10f);
    }
#pragma unroll
    for (int o = 16; o > 0; o >>= 1) ent += __shfl_down_sync(0xffffffffu, ent, o);
    __shared__ float red[16];
    int lane = tid & 31, wid = tid >> 5;
    if (lane == 0) red[wid] = ent;
    __syncthreads();
    if (tid == 0) {
        float tot = 0.f;
#pragma unroll
        for (int w = 0; w < 16; w++) tot += red[w];
        float lu = tot / (512.f + 1e-8f);
        float acc = 0.f;
#pragma unroll
        for (int i = 0; i < BB; i++) acc += g_inter[i] / (g_union[i] + 1e-8f);
        float lb = 1.f - acc * (1.f / 16.f);
        float ld = g_dbc * (1.f / ((float)BB * (float)NN));
        out[0] = lu;
        out[1] = lb;
        out[2] = ld;
        out[3] = 0.3f * lu + 0.2f * lb + 0.2f * ld;
    }
}

// ---------------------------------------------------------------------------
extern "C" void kernel_launch(void* const* d_in, const int* in_sizes, int n_in,
                              void* d_out, int out_size) {
    const int*   sem   = (const int*)d_in[0];
    const float* masks = (const float*)d_in[1];
    const float* depth = (const float*)d_in[2];
    float* out = (float*)d_out;

    pack_kernel<<<(BB * NN / 4) / 256, 256>>>(sem);        // 1024 blocks
    hist_kernel<<<BB * MM, T1>>>(masks);                   // 512 blocks
    pixel_kernel<<<BB * HH, 256>>>(masks, depth);          // 4096 blocks
    finalize_kernel<<<1, 512>>>(out);
}

// round 2
// speedup vs baseline: 1.4240x; 1.4240x over previous
#include <cuda_runtime.h>
#include <math.h>

#define BB 16
#define MM 32
#define HH 256
#define WW 256
#define NN 65536      // HH*WW
#define CC 27
#define T1 256        // threads for hist kernel

// ---- scratch (device globals; unique writers everywhere -> no atomics) ----
__device__ __align__(16) unsigned char g_sem8[BB * NN];  // packed semantic classes
__device__ float g_entArr[BB * MM];                      // per-(b,m) entropy
__device__ float g_rowI[BB * HH];                        // per-(b,row) intersection
__device__ float g_rowU[BB * HH];                        // per-(b,row) union
__device__ float g_rowD[BB * HH];                        // per-(b,row) dbc partial

// ---------------------------------------------------------------------------
// Kernel A: pack sem -> uint8 AND compute boundary / depth-coherence losses.
// grid = B*H blocks (one image row), 256 threads (one per column).
// Reads raw int32 sem for neighbors (no ordering dependency on the pack).
// ---------------------------------------------------------------------------
__global__ __launch_bounds__(256) void pixel_kernel(const int* __restrict__ sem,
                                                    const float* __restrict__ masks,
                                                    const float* __restrict__ depth) {
    const int b = blockIdx.x >> 8;
    const int y = blockIdx.x & 255;
    const int x = threadIdx.x;
    const int n = (y << 8) | x;
    const size_t idx = ((size_t)b << 16) + (size_t)n;

    int s  = sem[idx];
    int sl = x ? sem[idx - 1]  : s;
    int su = y ? sem[idx - WW] : s;
    g_sem8[idx] = (unsigned char)s;
    float semb = (s != sl || s != su) ? 1.f : 0.f;

    const float* m0 = masks + ((size_t)b * MM) * NN;   // m = 0 plane
    float mm = m0[n];
    float ml = x ? m0[n - 1]  : mm;
    float mu = y ? m0[n - WW] : mm;
    float instb = (fabsf(mm - ml) > 0.3f || fabsf(mm - mu) > 0.3f) ? 1.f : 0.f;

    float inter = semb * instb;
    float uni   = fmaxf(semb, instb);

    float d  = depth[idx];
    float dl = x ? depth[idx - 1]  : d;
    float du = y ? depth[idx - WW] : d;
    float gx = d - dl, gy = d - du;
    float ss = gx * gx + gy * gy;
    float db = sqrtf(fmaxf(ss, 1e-24f));
    float dbc = fminf(db, 2.f);
    float contrib = (1.f + 3.f * dbc) * (1.f - semb) * dbc;

#pragma unroll
    for (int o = 16; o > 0; o >>= 1) {
        inter   += __shfl_down_sync(0xffffffffu, inter,   o);
        uni     += __shfl_down_sync(0xffffffffu, uni,     o);
        contrib += __shfl_down_sync(0xffffffffu, contrib, o);
    }
    __shared__ float r0[8], r1[8], r2[8];
    int lane = threadIdx.x & 31, wid = threadIdx.x >> 5;
    if (lane == 0) { r0[wid] = inter; r1[wid] = uni; r2[wid] = contrib; }
    __syncthreads();
    if (threadIdx.x == 0) {
        float a = 0.f, u = 0.f, c2 = 0.f;
#pragma unroll
        for (int w = 0; w < 8; w++) { a += r0[w]; u += r1[w]; c2 += r2[w]; }
        g_rowI[blockIdx.x] = a;
        g_rowU[blockIdx.x] = u;
        g_rowD[blockIdx.x] = c2;
    }
}

// ---------------------------------------------------------------------------
// Kernel B: per-(b,m) masked histogram + entropy.
// grid = 512 blocks (one per (b,m)), 256 threads.
// Column-major private histograms: s_hist[c*T1 + tid] -> bank = tid%32,
// constant per lane => every LDS/STS RMW is conflict-free (1 wavefront).
// ---------------------------------------------------------------------------
__global__ __launch_bounds__(T1) void hist_kernel(const float* __restrict__ masks) {
    __shared__ float s_hist[CC * T1];         // 27*256*4 = 27,648 B
    __shared__ float s_red[T1 / 32][CC];

    const int block = blockIdx.x;             // block = b*32 + m
    const int b     = block >> 5;
    const int tid   = threadIdx.x;
    const int lane  = tid & 31;
    const int wid   = tid >> 5;

    float* my = s_hist + tid;                 // my[c<<8] is this thread's bin c
#pragma unroll
    for (int c = 0; c < CC; c++) my[c << 8] = 0.f;

    const float4* mp = (const float4*)masks + (size_t)block * (NN / 4);
    const uchar4* sp = (const uchar4*)(g_sem8 + (size_t)b * NN);

#pragma unroll 4
    for (int j = 0; j < NN / 4 / T1; j++) {   // 64 iterations, 4 elems each
        int i = tid + j * T1;
        float4 v = mp[i];
        uchar4 cl = sp[i];
        my[((int)cl.x) << 8] += v.x;
        my[((int)cl.y) << 8] += v.y;
        my[((int)cl.z) << 8] += v.z;
        my[((int)cl.w) << 8] += v.w;
    }
    __syncwarp();

    // pull own column into registers, butterfly-reduce across the warp
    float h[CC];
#pragma unroll
    for (int c = 0; c < CC; c++) h[c] = my[c << 8];
#pragma unroll
    for (int o = 16; o > 0; o >>= 1) {
#pragma unroll
        for (int c = 0; c < CC; c++) h[c] += __shfl_xor_sync(0xffffffffu, h[c], o);
    }
    if (lane == 0) {
#pragma unroll
        for (int c = 0; c < CC; c++) s_red[wid][c] = h[c];
    }
    __syncthreads();

    // warp 0: combine the 8 warp partials, compute entropy, write result
    if (wid == 0) {
        float t = 0.f;
        if (lane < CC) {
#pragma unroll
            for (int w = 0; w < T1 / 32; w++) t += s_red[w][lane];
        }
        float msum = t;
#pragma unroll
        for (int o = 16; o > 0; o >>= 1) msum += __shfl_xor_sync(0xffffffffu, msum, o);
        msum += 1e-6f;
        float p = t / msum;
        p = fminf(fmaxf(p, 1e-7f), 1.0f);
        float term = (lane < CC && p > 1e-6f) ? -p * __logf(p + 1e-10f) : 0.f;
#pragma unroll
        for (int o = 16; o > 0; o >>= 1) term += __shfl_xor_sync(0xffffffffu, term, o);
        if (lane == 0) g_entArr[block] = term;
    }
}

// ---------------------------------------------------------------------------
// Kernel C: finalize. 1 block, 512 threads. Warp w = batch b for boundary sums.
// ---------------------------------------------------------------------------
__global__ __launch_bounds__(512) void finalize_kernel(float* __restrict__ out) {
    const int tid  = threadIdx.x;
    const int lane = tid & 31;
    const int wid  = tid >> 5;     // 16 warps, one per batch b

    // entropy sum over 512 (b,m) pairs
    float e = g_entArr[tid];
    // boundary: warp wid handles batch b = wid; each lane sums 8 rows
    float I = 0.f, U = 0.f, D = 0.f;
#pragma unroll
    for (int r = 0; r < 8; r++) {
        int row = (wid << 8) + (lane << 3) + r;
        I += g_rowI[row];
        U += g_rowU[row];
        D += g_rowD[row];
    }
#pragma unroll
    for (int o = 16; o > 0; o >>= 1) {
        e += __shfl_xor_sync(0xffffffffu, e, o);
        I += __shfl_xor_sync(0xffffffffu, I, o);
        U += __shfl_xor_sync(0xffffffffu, U, o);
        D += __shfl_xor_sync(0xffffffffu, D, o);
    }
    __shared__ float sE[16], sR[16], sD[16];
    if (lane == 0) {
        sE[wid] = e;
        sR[wid] = I / (U + 1e-8f);
        sD[wid] = D;
    }
    __syncthreads();
    if (tid == 0) {
        float etot = 0.f, rtot = 0.f, dtot = 0.f;
#pragma unroll
        for (int w = 0; w < 16; w++) { etot += sE[w]; rtot += sR[w]; dtot += sD[w]; }
        float lu = etot / (512.f + 1e-8f);
        float lb = 1.f - rtot * (1.f / 16.f);
        float ld = dtot * (1.f / ((float)BB * (float)NN));
        out[0] = lu;
        out[1] = lb;
        out[2] = ld;
        out[3] = 0.3f * lu + 0.2f * lb + 0.2f * ld;
    }
}

// ---------------------------------------------------------------------------
extern "C" void kernel_launch(void* const* d_in, const int* in_sizes, int n_in,
                              void* d_out, int out_size) {
    const int*   sem   = (const int*)d_in[0];
    const float* masks = (const float*)d_in[1];
    const float* depth = (const float*)d_in[2];
    float* out = (float*)d_out;

    pixel_kernel<<<BB * HH, 256>>>(sem, masks, depth);   // 4096 blocks: pack + losses
    hist_kernel<<<BB * MM, T1>>>(masks);                 // 512 blocks
    finalize_kernel<<<1, 512>>>(out);
}

// round 3
// speedup vs baseline: 1.7554x; 1.2328x over previous
#include <cuda_runtime.h>
#include <math.h>

#define BB 16
#define MM 32
#define WW 256
#define NN 65536      // 256*256
#define CC 27
#define T1 256

// ---- scratch (unique writer per element -> no atomics, no zero-init) ----
__device__ float g_entArr[BB * MM];   // per-(b,m) entropy
__device__ float g_blkI[BB * MM];     // per-block boundary intersection partial
__device__ float g_blkU[BB * MM];     // per-block boundary union partial
__device__ float g_blkD[BB * MM];     // per-block dbc partial

// ---------------------------------------------------------------------------
// Fused kernel: 512 blocks (one per (b,m)), 256 threads.
//  Part 1: each block computes boundary/depth losses on a 2048-px slice
//          (slice index == block index; always within batch b = block>>5).
//  Part 2: masked class histogram for its (b,m) plane via per-thread private
//          column-major smem bins (bank = tid%32, conflict-free RMW), then
//          in-block entropy.
// ---------------------------------------------------------------------------
__global__ __launch_bounds__(T1) void fused_kernel(const int* __restrict__ sem,
                                                   const float* __restrict__ masks,
                                                   const float* __restrict__ depth) {
    __shared__ float s_hist[CC * T1];          // 27,648 B
    __shared__ float s_red[T1 / 32][CC];
    __shared__ float rI[T1 / 32], rU[T1 / 32], rD[T1 / 32];

    const int block = blockIdx.x;              // b*32 + m
    const int b     = block >> 5;
    const int tid   = threadIdx.x;
    const int lane  = tid & 31;
    const int wid   = tid >> 5;

    float* my = s_hist + tid;                  // bin c at my[c*T1]
#pragma unroll
    for (int c = 0; c < CC; c++) my[c * T1] = 0.f;

    // batch-local vector bases
    const int4*   semv = (const int4*)sem + ((size_t)b << 14);
    const float4* m0v  = (const float4*)(masks + (size_t)b * MM * NN);  // m=0 plane
    const float4* dv   = (const float4*)depth + ((size_t)b << 14);
    const int*    semS = sem + ((size_t)b << 16);
    const float*  m0S  = masks + (size_t)b * MM * NN;
    const float*  dS   = depth + ((size_t)b << 16);

    // ---- Part 1: pixel-loss slice (512 groups of 4 px, 2 per thread) ----
    float inter = 0.f, uni = 0.f, contrib = 0.f;
    const int base_n = (block & 31) << 11;     // slice start within batch
#pragma unroll
    for (int q = 0; q < 2; q++) {
        int n  = base_n + ((q * T1 + tid) << 2);   // first px of group
        int gi = n >> 2;
        int y  = n >> 8, x = n & 255;
        int4   s4  = semv[gi];
        float4 m4  = m0v[gi];
        float4 d4  = dv[gi];
        int giu = (y > 0) ? gi - 64 : gi;          // row above (replicate at y==0)
        int4   s4u = semv[giu];
        float4 m4u = m0v[giu];
        float4 d4u = dv[giu];
        int sl0; float ml0, dl0;
        if (x > 0) { sl0 = semS[n - 1]; ml0 = m0S[n - 1]; dl0 = dS[n - 1]; }
        else       { sl0 = s4.x;        ml0 = m4.x;       dl0 = d4.x; }

        int   s[4]  = {s4.x, s4.y, s4.z, s4.w};
        int   sl[4] = {sl0, s4.x, s4.y, s4.z};
        int   su[4] = {s4u.x, s4u.y, s4u.z, s4u.w};
        float m[4]  = {m4.x, m4.y, m4.z, m4.w};
        float ml[4] = {ml0, m4.x, m4.y, m4.z};
        float mu[4] = {m4u.x, m4u.y, m4u.z, m4u.w};
        float d[4]  = {d4.x, d4.y, d4.z, d4.w};
        float dl[4] = {dl0, d4.x, d4.y, d4.z};
        float du[4] = {d4u.x, d4u.y, d4u.z, d4u.w};
#pragma unroll
        for (int e = 0; e < 4; e++) {
            float semb  = (s[e] != sl[e] || s[e] != su[e]) ? 1.f : 0.f;
            float instb = (fabsf(m[e] - ml[e]) > 0.3f ||
                           fabsf(m[e] - mu[e]) > 0.3f) ? 1.f : 0.f;
            inter += semb * instb;
            uni   += fmaxf(semb, instb);
            float gx = d[e] - dl[e], gy = d[e] - du[e];
            float ss = gx * gx + gy * gy;
            float db = sqrtf(fmaxf(ss, 1e-24f));
            float dbc = fminf(db, 2.f);
            contrib += (1.f + 3.f * dbc) * (1.f - semb) * dbc;
        }
    }
#pragma unroll
    for (int o = 16; o > 0; o >>= 1) {
        inter   += __shfl_down_sync(0xffffffffu, inter,   o);
        uni     += __shfl_down_sync(0xffffffffu, uni,     o);
        contrib += __shfl_down_sync(0xffffffffu, contrib, o);
    }
    if (lane == 0) { rI[wid] = inter; rU[wid] = uni; rD[wid] = contrib; }

    // ---- Part 2: masked histogram (64 groups/thread, 2 per iter) ----
    const float4* mp = (const float4*)masks + (size_t)block * (NN / 4);
#pragma unroll 4
    for (int j = 0; j < 32; j++) {
        int i0 = tid + j * 512;
        float4 v0 = mp[i0];
        float4 v1 = mp[i0 + 256];
        int4   c0 = semv[i0];
        int4   c1 = semv[i0 + 256];
        my[c0.x * T1] += v0.x;
        my[c0.y * T1] += v0.y;
        my[c0.z * T1] += v0.z;
        my[c0.w * T1] += v0.w;
        my[c1.x * T1] += v1.x;
        my[c1.y * T1] += v1.y;
        my[c1.z * T1] += v1.z;
        my[c1.w * T1] += v1.w;
    }
    __syncwarp();

    // butterfly-reduce each thread's 27 bins across the warp
    float h[CC];
#pragma unroll
    for (int c = 0; c < CC; c++) h[c] = my[c * T1];
#pragma unroll
    for (int o = 16; o > 0; o >>= 1) {
#pragma unroll
        for (int c = 0; c < CC; c++) h[c] += __shfl_xor_sync(0xffffffffu, h[c], o);
    }
    if (lane == 0) {
#pragma unroll
        for (int c = 0; c < CC; c++) s_red[wid][c] = h[c];
    }
    __syncthreads();

    if (wid == 0) {
        // combine 8 warp partials, entropy over 27 classes
        float t = 0.f;
        if (lane < CC) {
#pragma unroll
            for (int w = 0; w < T1 / 32; w++) t += s_red[w][lane];
        }
        float msum = t;
#pragma unroll
        for (int o = 16; o > 0; o >>= 1) msum += __shfl_xor_sync(0xffffffffu, msum, o);
        msum += 1e-6f;
        float p = t / msum;
        p = fminf(fmaxf(p, 1e-7f), 1.0f);
        float term = (lane < CC && p > 1e-6f) ? -p * __logf(p + 1e-10f) : 0.f;
#pragma unroll
        for (int o = 16; o > 0; o >>= 1) term += __shfl_xor_sync(0xffffffffu, term, o);
        if (lane == 0) g_entArr[block] = term;
    } else if (wid == 1 && lane == 0) {
        float I = 0.f, U = 0.f, D = 0.f;
#pragma unroll
        for (int w = 0; w < T1 / 32; w++) { I += rI[w]; U += rU[w]; D += rD[w]; }
        g_blkI[block] = I;
        g_blkU[block] = U;
        g_blkD[block] = D;
    }
}

// ---------------------------------------------------------------------------
// Finalize: 1 block, 512 threads. Warp w owns batch b=w for the IoU ratio.
// ---------------------------------------------------------------------------
__global__ __launch_bounds__(512) void finalize_kernel(float* __restrict__ out) {
    const int tid  = threadIdx.x;
    const int lane = tid & 31;
    const int wid  = tid >> 5;     // 16 warps = 16 batches

    float e = g_entArr[tid];
    float I = g_blkI[tid];         // tid = w*32+lane = block index; batch = w
    float U = g_blkU[tid];
    float D = g_blkD[tid];
#pragma unroll
    for (int o = 16; o > 0; o >>= 1) {
        e += __shfl_xor_sync(0xffffffffu, e, o);
        I += __shfl_xor_sync(0xffffffffu, I, o);
        U += __shfl_xor_sync(0xffffffffu, U, o);
        D += __shfl_xor_sync(0xffffffffu, D, o);
    }
    __shared__ float sE[16], sR[16], sD[16];
    if (lane == 0) {
        sE[wid] = e;
        sR[wid] = I / (U + 1e-8f);
        sD[wid] = D;
    }
    __syncthreads();
    if (tid == 0) {
        float etot = 0.f, rtot = 0.f, dtot = 0.f;
#pragma unroll
        for (int w = 0; w < 16; w++) { etot += sE[w]; rtot += sR[w]; dtot += sD[w]; }
        float lu = etot / (512.f + 1e-8f);
        float lb = 1.f - rtot * (1.f / 16.f);
        float ld = dtot * (1.f / ((float)BB * (float)NN));
        out[0] = lu;
        out[1] = lb;
        out[2] = ld;
        out[3] = 0.3f * lu + 0.2f * lb + 0.2f * ld;
    }
}

// ---------------------------------------------------------------------------
extern "C" void kernel_launch(void* const* d_in, const int* in_sizes, int n_in,
                              void* d_out, int out_size) {
    const int*   sem   = (const int*)d_in[0];
    const float* masks = (const float*)d_in[1];
    const float* depth = (const float*)d_in[2];
    float* out = (float*)d_out;

    fused_kernel<<<BB * MM, T1>>>(sem, masks, depth);   // 512 blocks
    finalize_kernel<<<1, 512>>>(out);
}